// round 5
// baseline (speedup 1.0000x reference)
#include <cuda_runtime.h>
#include <math.h>
#include <stdint.h>

// ---------------------------------------------------------------------------
// C=64 channels, 10x10x10 pixel-shuffle unfold -> M = 64000 rows.
// Branch dims: axi D=140 (w=5,7,4), cor D=112 (w=4,4,7), sag D=160 (w=4,8,5).
// atlas0: 64000 x 120 (w=5,6,4), shared across branches.
// Algebra:
//   G0 = atlas0^T B (120 x D);  G[i,j] = G0[colmap(i), j]
//   S = Wq^T G Wk + (Wq^T sA) bk^T + bq (sB^T Wk + M bk)^T,  sA[i]=s0[colmap(i)]
//   P = softmax_rows(S);  cross = B (Wv P^T) + 1 (P bv)^T   (scattered to out)
// B is never materialized: B[m,j] = g_pad[ccBase(m) + mterm(m) + jterm(j)]
// Big GEMMs run on tensor cores: mma.sync.m16n8k8.tf32 with 3xTF32 splitting
// (hi=rna-tf32(x), lo=x-hi; passes hi*hi + hi*lo + lo*hi) -> fp32-grade accuracy.
// ---------------------------------------------------------------------------

#define NCH 5   // K-split chunks per channel in gemmG0 (200 rows each)

__device__ float g_atlas0[64000*120];
__device__ float g_pad[64000*160];     // padded, transpose-folded feat (reused per branch)
__device__ float g_G0p[NCH*120*160];   // split-K partial G0 slabs
__device__ float g_G0[120*160];
__device__ float g_T[160*160];
__device__ float g_S[160*160];
__device__ float g_U[160*160];
__device__ float g_s0[120];
__device__ float g_sB[160];
__device__ float g_Z[160];
__device__ float g_pb[160];

template<int BR> struct Cfg;
// axi: internal = input (64,48,66,38); pad->(50,70,40) pb(1,2,1); w=(5,7,4); D=140
template<> struct Cfg<0>{
  static constexpr int D=140, W0=5,W1=7,W2=4, P0=1,P1=2,P2=1, I0=48,I1=66,I2=38;
  static constexpr int PS0=50,PS1=70,PS2=40, OUT0=0;
};
// cor: internal = cor.transpose(0,1,2,4,3) -> (64,38,38,66); pb(1,1,2); w=(4,4,7); D=112
template<> struct Cfg<1>{
  static constexpr int D=112, W0=4,W1=4,W2=7, P0=1,P1=1,P2=2, I0=38,I1=38,I2=66;
  static constexpr int PS0=40,PS1=40,PS2=70, OUT0=7704576;
};
// sag: internal = sag.transpose(0,1,4,3,2) -> (64,38,78,48); pb(1,1,1); w=(4,8,5); D=160
template<> struct Cfg<2>{
  static constexpr int D=160, W0=4,W1=8,W2=5, P0=1,P1=1,P2=1, I0=38,I1=78,I2=48;
  static constexpr int PS0=40,PS1=80,PS2=50, OUT0=13804032;
};

// gather from raw input, folding the branch transpose; 0 outside valid region
template<int BR>
__device__ __forceinline__ float loadFeat(const float* __restrict__ f, int cc, int z, int y, int x){
  if ((unsigned)z >= (unsigned)Cfg<BR>::I0 ||
      (unsigned)y >= (unsigned)Cfg<BR>::I1 ||
      (unsigned)x >= (unsigned)Cfg<BR>::I2) return 0.f;
  if constexpr (BR==0) return f[((cc*48+z)*66+y)*38+x];
  else if constexpr (BR==1) return f[((cc*38+z)*66+x)*38+y];
  else                      return f[((cc*48+x)*78+y)*38+z];
}

// scatter index into concatenated output, folding inverse branch transpose
template<int BR>
__device__ __forceinline__ int outIndex(int cc, int z, int y, int x){
  if constexpr (BR==0) return ((cc*48+z)*66+y)*38+x;
  else if constexpr (BR==1) return Cfg<1>::OUT0 + ((cc*38+z)*66+x)*38+y;
  else                      return Cfg<2>::OUT0 + ((cc*48+x)*78+y)*38+z;
}

// composed nearest-neighbor chain: branch spatial col -> atlas0 col (5,6,4 grid)
template<int BR>
__device__ __forceinline__ int atlasCol(int j){
  if constexpr (BR==0){
    int z=j/28, y=(j/4)%7, x=j%4;            // (5,7,4)
    int y0=(y*6)/7;
    return (z*6+y0)*4+x;
  } else if constexpr (BR==1){
    int z=j/28, y=(j/7)%4, x=j%7;            // (4,4,7) <- (5,7,4)
    int z1=(z*5)/4, y1=(y*7)/4, x1=(x*4)/7;
    int y0=(y1*6)/7;
    return (z1*6+y0)*4+x1;
  } else {
    int z=j/40, y=(j/5)%8, x=j%5;            // (4,8,5) <- (4,4,7) <- (5,7,4)
    int z2=z,  y2=y/2,     x2=(x*7)/5;
    int z1=(z2*5)/4, y1=(y2*7)/4, x1=(x2*4)/7;
    int y0=(y1*6)/7;
    return (z1*6+y0)*4+x1;
  }
}

// ---------------- tf32 helpers ----------------

__device__ __forceinline__ float tf32_hi(float x){
  uint32_t u; asm("cvt.rna.tf32.f32 %0, %1;" : "=r"(u) : "f"(x));
  return __uint_as_float(u);
}

__device__ __forceinline__ void mma_tf32(float c[4],
    uint32_t a0, uint32_t a1, uint32_t a2, uint32_t a3,
    uint32_t b0, uint32_t b1){
  asm volatile(
    "mma.sync.aligned.m16n8k8.row.col.f32.tf32.tf32.f32 "
    "{%0,%1,%2,%3}, {%4,%5,%6,%7}, {%8,%9}, {%0,%1,%2,%3};"
    : "+f"(c[0]), "+f"(c[1]), "+f"(c[2]), "+f"(c[3])
    : "r"(a0), "r"(a1), "r"(a2), "r"(a3), "r"(b0), "r"(b1));
}

// ---------------- kernels ----------------

__global__ void zero_small(){
  int t = blockIdx.x*256 + threadIdx.x;
  if (t < NCH*120*160) g_G0p[t] = 0.f;
  if (t < 120) g_s0[t]=0.f;
  if (t < 160) g_sB[t]=0.f;
}

__global__ void build_atlas0(const float* __restrict__ atlas){
  int idx = blockIdx.x*256 + threadIdx.x;
  if (idx >= 64000*120) return;
  int m = idx / 120, j = idx % 120;
  int cc = m / 1000, r = m % 1000;
  int a0 = r/100, a1 = (r/10)%10, a2 = r%10;
  int b0 = j/24, b1 = (j/4)%6, b2 = j%4;
  int z = a0*5 + b0 - 2, y = a1*6 + b1 - 2, x = a2*4 + b2 - 1;
  float v = 0.f;
  if ((unsigned)z < 46u && (unsigned)y < 56u && (unsigned)x < 38u)
    v = atlas[((cc*46+z)*56+y)*38+x];
  g_atlas0[idx] = v;
}

// padded, transpose-folded feat. grid = 64*PS0 blocks, block 256 looping a plane.
template<int BR>
__global__ void build_pad(const float* __restrict__ feat){
  constexpr int PS0=Cfg<BR>::PS0, PS1=Cfg<BR>::PS1, PS2=Cfg<BR>::PS2;
  int bz = blockIdx.x;
  int cc = bz / PS0, zp = bz % PS0;
  int z = zp - Cfg<BR>::P0;
  float* dst = g_pad + (size_t)bz * (PS1*PS2);
  for (int i = threadIdx.x; i < PS1*PS2; i += blockDim.x){
    int yp = i / PS2, xp = i % PS2;
    dst[i] = loadFeat<BR>(feat, cc, z, yp - Cfg<BR>::P1, xp - Cfg<BR>::P2);
  }
}

// G0 = atlas0^T B (120 x D). K split 320-way: blockIdx.z = cc*NCH + chunk
// (200 rows per chunk). B gathered from g_pad via separable address.
// Tensor-core 3xTF32 core. 8 warps: warp_i = wid>>2 (32-row half),
// warp_j = wid&3 (16-col slice). smem tiles [k=8][72] hi/lo (stride 72 ->
// conflict-free frag loads). Partials into g_G0p[chunk].
template<int BR>
__global__ void __launch_bounds__(256) gemmG0(){
  constexpr int D=Cfg<BR>::D, W0=Cfg<BR>::W0, W1=Cfg<BR>::W1, W2=Cfg<BR>::W2;
  constexpr int S1=Cfg<BR>::PS1*Cfg<BR>::PS2, S2=Cfg<BR>::PS2;
  __shared__ float Ahi[2][8][72], Alo[2][8][72];
  __shared__ float Bhi[2][8][72], Blo[2][8][72];
  __shared__ int mterm[200];
  __shared__ int jterm[64];
  int tj0 = blockIdx.x*64, ti0 = blockIdx.y*64;
  int zc = blockIdx.z;
  int cc = zc / NCH, ch = zc % NCH;
  int r0 = ch*200;
  int t = threadIdx.x;

  if (t < 200){
    int r = r0 + t;
    int a0=r/100, a1=(r/10)%10, a2=r%10;
    mterm[t] = (a0*W0)*S1 + (a1*W1)*S2 + (a2*W2);
  }
  if (t < 64){
    int j = tj0 + t;
    if (j < D){
      int b0=j/(W1*W2), b1=(j/W2)%W1, b2=j%W2;
      jterm[t] = b0*S1 + b1*S2 + b2;
    } else jterm[t] = 0;
  }
  __syncthreads();

  int lc = t & 63, lr = t >> 6;    // loader lanes: 64 cols x 4 row-groups
  bool jok = (tj0+lc) < D;
  bool iok = (ti0+lc) < 120;
  int jt = jterm[lc];
  const float* padc = g_pad + (size_t)cc * (1000*D);
  const float* atl  = g_atlas0 + (size_t)cc*(1000*120) + (size_t)r0*120 + ti0 + lc;

  int wid = t >> 5, lane = t & 31;
  int wi = wid >> 2, wj = wid & 3;     // warp tile coords
  int group = lane >> 2, tig = lane & 3;

  float acc[2][2][4];
  #pragma unroll
  for (int a=0;a<2;a++)
    #pragma unroll
    for (int b=0;b<2;b++)
      #pragma unroll
      for (int q=0;q<4;q++) acc[a][b][q]=0.f;
  float aCS = 0.f, bCS = 0.f;

  auto loadTile = [&](int it, int p){
    #pragma unroll
    for (int s=0;s<2;s++){
      int kk = lr + 4*s;
      int r = it*8 + kk;              // local row 0..199
      float a = iok ? atl[r*120] : 0.f;
      float b = jok ? padc[mterm[r] + jt] : 0.f;
      float ah = tf32_hi(a), bh = tf32_hi(b);
      Ahi[p][kk][lc] = ah; Alo[p][kk][lc] = a - ah;
      Bhi[p][kk][lc] = bh; Blo[p][kk][lc] = b - bh;
      aCS += a; bCS += b;
    }
  };

  loadTile(0, 0);
  __syncthreads();
  int p = 0;
  for (int it = 0; it < 25; it++){
    if (it + 1 < 25) loadTile(it+1, p^1);
    #pragma unroll
    for (int mt=0; mt<2; mt++){
      int ri = wi*32 + mt*16;
      uint32_t aH0 = __float_as_uint(Ahi[p][tig  ][ri+group]);
      uint32_t aH1 = __float_as_uint(Ahi[p][tig  ][ri+8+group]);
      uint32_t aH2 = __float_as_uint(Ahi[p][tig+4][ri+group]);
      uint32_t aH3 = __float_as_uint(Ahi[p][tig+4][ri+8+group]);
      uint32_t aL0 = __float_as_uint(Alo[p][tig  ][ri+group]);
      uint32_t aL1 = __float_as_uint(Alo[p][tig  ][ri+8+group]);
      uint32_t aL2 = __float_as_uint(Alo[p][tig+4][ri+group]);
      uint32_t aL3 = __float_as_uint(Alo[p][tig+4][ri+8+group]);
      #pragma unroll
      for (int nt=0; nt<2; nt++){
        int cj = wj*16 + nt*8;
        uint32_t bH0 = __float_as_uint(Bhi[p][tig  ][cj+group]);
        uint32_t bH1 = __float_as_uint(Bhi[p][tig+4][cj+group]);
        uint32_t bL0 = __float_as_uint(Blo[p][tig  ][cj+group]);
        uint32_t bL1 = __float_as_uint(Blo[p][tig+4][cj+group]);
        mma_tf32(acc[mt][nt], aH0,aH1,aH2,aH3, bH0,bH1);
        mma_tf32(acc[mt][nt], aH0,aH1,aH2,aH3, bL0,bL1);
        mma_tf32(acc[mt][nt], aL0,aL1,aL2,aL3, bH0,bH1);
      }
    }
    __syncthreads();
    p ^= 1;
  }

  float* slab = g_G0p + ch*(120*160);
  #pragma unroll
  for (int mt=0; mt<2; mt++){
    #pragma unroll
    for (int nt=0; nt<2; nt++){
      int i0 = ti0 + wi*32 + mt*16 + group;
      int j0 = tj0 + wj*16 + nt*8 + tig*2;
      float* c = acc[mt][nt];
      if (i0 < 120){
        if (j0   < D) atomicAdd(&slab[i0*D + j0],   c[0]);
        if (j0+1 < D) atomicAdd(&slab[i0*D + j0+1], c[1]);
      }
      if (i0+8 < 120){
        if (j0   < D) atomicAdd(&slab[(i0+8)*D + j0],   c[2]);
        if (j0+1 < D) atomicAdd(&slab[(i0+8)*D + j0+1], c[3]);
      }
    }
  }
  if (blockIdx.x==0 && iok) atomicAdd(&g_s0[ti0+lc], aCS);
  if (blockIdx.y==0 && jok) atomicAdd(&g_sB[tj0+lc], bCS);
}

// sum the NCH partial slabs into g_G0
template<int D>
__global__ void reduceG0(){
  int idx = blockIdx.x*256 + threadIdx.x;
  if (idx >= 120*D) return;
  float s = 0.f;
  #pragma unroll
  for (int c=0;c<NCH;c++) s += g_G0p[c*(120*160) + idx];
  g_G0[idx] = s;
}

// T = G*Wk (G = rowgather(G0)) ; Z[j] = sB.Wk[:,j] + M*bk[j]
template<int BR>
__global__ void smallT(const float* __restrict__ Wk, const float* __restrict__ bk){
  constexpr int D = Cfg<BR>::D;
  int idx = blockIdx.x*256 + threadIdx.x;
  if (idx < D*D){
    int p = idx/D, j = idx%D;
    int gp = atlasCol<BR>(p);
    float acc = 0.f;
    for (int r=0;r<D;r++) acc += g_G0[gp*D+r]*Wk[r*D+j];
    g_T[idx] = acc;
  }
  if (idx < D){
    float z = 0.f;
    for (int r=0;r<D;r++) z += g_sB[r]*Wk[r*D+idx];
    g_Z[idx] = z + 64000.f*bk[idx];
  }
}

// S = Wq^T T + (Wq^T sA) bk^T + bq Z^T,  sA[p] = s0[colmap(p)]
template<int BR>
__global__ void smallS(const float* __restrict__ Wq, const float* __restrict__ bq,
                       const float* __restrict__ bk){
  constexpr int D = Cfg<BR>::D;
  __shared__ float sAl[160];
  int t = threadIdx.x;
  if (t < D) sAl[t] = g_s0[atlasCol<BR>(t)];
  __syncthreads();
  int idx = blockIdx.x*256 + t;
  if (idx >= D*D) return;
  int i = idx/D, j = idx%D;
  float acc = 0.f, acc2 = 0.f;
  for (int p=0;p<D;p++){
    float w = Wq[p*D+i];
    acc  += w * g_T[p*D+j];
    acc2 += w * sAl[p];
  }
  g_S[idx] = acc + acc2*bk[j] + bq[i]*g_Z[j];
}

template<int D>
__global__ void softmaxK(){
  __shared__ float red[256];
  int i = blockIdx.x, t = threadIdx.x;
  float v = (t < D) ? g_S[i*D+t] : -3.4e38f;
  red[t] = v; __syncthreads();
  for (int s=128; s>0; s>>=1){ if (t<s) red[t]=fmaxf(red[t],red[t+s]); __syncthreads(); }
  float mx = red[0]; __syncthreads();
  float e = (t < D) ? expf(v - mx) : 0.f;
  red[t] = e; __syncthreads();
  for (int s=128; s>0; s>>=1){ if (t<s) red[t]+=red[t+s]; __syncthreads(); }
  float sum = red[0];
  if (t < D) g_S[i*D+t] = e / sum;
}

// U[r,i] = Wv[r,:].P[i,:] ; pb[i] = P[i,:].bv
template<int D>
__global__ void smallU(const float* __restrict__ Wv, const float* __restrict__ bv){
  int idx = blockIdx.x*256 + threadIdx.x;
  if (idx >= D*D) return;
  int rr = idx/D, i = idx%D;
  float acc = 0.f;
  for (int j=0;j<D;j++) acc += Wv[rr*D+j]*g_S[i*D+j];
  g_U[idx] = acc;
  if (idx < D){
    float a = 0.f;
    for (int j=0;j<D;j++) a += g_S[idx*D+j]*bv[j];
    g_pb[idx] = a;
  }
}

// cross = Bm*U + pb : Bm gathered from g_pad (rows m, cols k over D),
// U (k x n). Tensor-core 3xTF32 core, same warp layout as gemmG0.
// Scatter (fold + crop + inverse transpose) straight to out.
template<int BR>
__global__ void __launch_bounds__(256) crossK(float* __restrict__ out){
  constexpr int D=Cfg<BR>::D, W0=Cfg<BR>::W0, W1=Cfg<BR>::W1, W2=Cfg<BR>::W2;
  constexpr int S1=Cfg<BR>::PS1*Cfg<BR>::PS2, S2=Cfg<BR>::PS2;
  constexpr int KT = (D + 7) / 8;
  __shared__ float Ahi[2][8][72], Alo[2][8][72];
  __shared__ float Bhi[2][8][72], Blo[2][8][72];
  __shared__ int mterm[64];
  __shared__ int jterm[160];
  int n0 = blockIdx.x*64, m0 = blockIdx.y*64;
  int t = threadIdx.x;

  if (t < 64){
    int m = m0 + t;
    int cc = m/1000, r = m%1000;
    int a0 = r/100, a1 = (r/10)%10, a2 = r%10;
    mterm[t] = cc*(1000*D) + (a0*W0)*S1 + (a1*W1)*S2 + (a2*W2);
  }
  if (t < D){
    int b0=t/(W1*W2), b1=(t/W2)%W1, b2=t%W2;
    jterm[t] = b0*S1 + b1*S2 + b2;
  }
  __syncthreads();

  int lc = t & 63, lr = t >> 6;
  int mt_ = mterm[lc];
  bool nok = (n0+lc) < D;

  int wid = t >> 5, lane = t & 31;
  int wi = wid >> 2, wj = wid & 3;
  int group = lane >> 2, tig = lane & 3;

  float acc[2][2][4];
  #pragma unroll
  for (int a=0;a<2;a++)
    #pragma unroll
    for (int b=0;b<2;b++)
      #pragma unroll
      for (int q=0;q<4;q++) acc[a][b][q]=0.f;

  auto loadTile = [&](int kc, int p){
    int k0 = kc*8;
    #pragma unroll
    for (int s=0;s<2;s++){
      int kk = lr + 4*s;
      int k = k0 + kk;
      float a = (k < D) ? g_pad[mt_ + jterm[k]] : 0.f;          // Bm[m=lc][k]
      float b = (k < D && nok) ? g_U[k*D + n0 + lc] : 0.f;      // U[k][n=lc]
      float ah = tf32_hi(a), bh = tf32_hi(b);
      Ahi[p][kk][lc] = ah; Alo[p][kk][lc] = a - ah;
      Bhi[p][kk][lc] = bh; Blo[p][kk][lc] = b - bh;
    }
  };

  loadTile(0, 0);
  __syncthreads();
  int p = 0;
  for (int kc=0; kc<KT; kc++){
    if (kc + 1 < KT) loadTile(kc+1, p^1);
    #pragma unroll
    for (int mt=0; mt<2; mt++){
      int ri = wi*32 + mt*16;
      uint32_t aH0 = __float_as_uint(Ahi[p][tig  ][ri+group]);
      uint32_t aH1 = __float_as_uint(Ahi[p][tig  ][ri+8+group]);
      uint32_t aH2 = __float_as_uint(Ahi[p][tig+4][ri+group]);
      uint32_t aH3 = __float_as_uint(Ahi[p][tig+4][ri+8+group]);
      uint32_t aL0 = __float_as_uint(Alo[p][tig  ][ri+group]);
      uint32_t aL1 = __float_as_uint(Alo[p][tig  ][ri+8+group]);
      uint32_t aL2 = __float_as_uint(Alo[p][tig+4][ri+group]);
      uint32_t aL3 = __float_as_uint(Alo[p][tig+4][ri+8+group]);
      #pragma unroll
      for (int nt=0; nt<2; nt++){
        int cj = wj*16 + nt*8;
        uint32_t bH0 = __float_as_uint(Bhi[p][tig  ][cj+group]);
        uint32_t bH1 = __float_as_uint(Bhi[p][tig+4][cj+group]);
        uint32_t bL0 = __float_as_uint(Blo[p][tig  ][cj+group]);
        uint32_t bL1 = __float_as_uint(Blo[p][tig+4][cj+group]);
        mma_tf32(acc[mt][nt], aH0,aH1,aH2,aH3, bH0,bH1);
        mma_tf32(acc[mt][nt], aH0,aH1,aH2,aH3, bL0,bL1);
        mma_tf32(acc[mt][nt], aL0,aL1,aL2,aL3, bH0,bH1);
      }
    }
    __syncthreads();
    p ^= 1;
  }

  // scatter epilogue: each thread owns rows {ri+group, ri+8+group} and
  // cols {j0, j0+1} per (mt,nt) tile
  #pragma unroll
  for (int mt=0; mt<2; mt++){
    #pragma unroll
    for (int rr=0; rr<2; rr++){
      int m = m0 + wi*32 + mt*16 + rr*8 + group;
      int cc = m/1000, r = m%1000;
      int a0 = r/100, a1 = (r/10)%10, a2 = r%10;
      int zb = a0*W0 - Cfg<BR>::P0;
      int yb = a1*W1 - Cfg<BR>::P1;
      int xb = a2*W2 - Cfg<BR>::P2;
      #pragma unroll
      for (int nt=0; nt<2; nt++){
        int j0 = n0 + wj*16 + nt*8 + tig*2;
        #pragma unroll
        for (int jj=0; jj<2; jj++){
          int j = j0 + jj;
          if (j >= D) continue;
          int b0 = j/(W1*W2), b1 = (j/W2)%W1, b2 = j%W2;
          int z = zb + b0, y = yb + b1, x = xb + b2;
          if ((unsigned)z < (unsigned)Cfg<BR>::I0 &&
              (unsigned)y < (unsigned)Cfg<BR>::I1 &&
              (unsigned)x < (unsigned)Cfg<BR>::I2){
            out[outIndex<BR>(cc,z,y,x)] = acc[mt][nt][rr*2+jj] + g_pb[j];
          }
        }
      }
    }
  }
}

// ---------------- host orchestration ----------------

template<int BR>
static void runBranch(const float* feat, void* const* w, float* out){
  constexpr int D = Cfg<BR>::D;
  const float *Wq=(const float*)w[0], *bq=(const float*)w[1];
  const float *Wk=(const float*)w[2], *bk=(const float*)w[3];
  const float *Wv=(const float*)w[4], *bv=(const float*)w[5];

  zero_small<<<(NCH*120*160+255)/256, 256>>>();
  build_pad<BR><<<64*Cfg<BR>::PS0, 256>>>(feat);

  dim3 gg((D+63)/64, 2, 64*NCH);
  gemmG0<BR><<<gg, 256>>>();
  reduceG0<D><<<(120*D+255)/256, 256>>>();

  int nb = (D*D+255)/256;
  smallT<BR><<<nb, 256>>>(Wk, bk);
  smallS<BR><<<nb, 256>>>(Wq, bq, bk);
  softmaxK<D><<<D, 256>>>();
  smallU<D><<<nb, 256>>>(Wv, bv);

  dim3 gc((D+63)/64, 1000);
  crossK<BR><<<gc, 256>>>(out);
}

extern "C" void kernel_launch(void* const* d_in, const int* in_sizes, int n_in,
                              void* d_out, int out_size){
  (void)in_sizes; (void)n_in; (void)out_size;
  const float* axi   = (const float*)d_in[0];
  const float* cor   = (const float*)d_in[1];
  const float* sag   = (const float*)d_in[2];
  const float* atlas = (const float*)d_in[3];
  float* out = (float*)d_out;

  build_atlas0<<<(64000*120+255)/256, 256>>>(atlas);

  runBranch<0>(axi, d_in + 4,  out);
  runBranch<1>(cor, d_in + 10, out);
  runBranch<2>(sag, d_in + 16, out);
}